// round 17
// baseline (speedup 1.0000x reference)
#include <cuda_runtime.h>

#define NN 50000
#define NE 800000
#define L 128
#define KEFF 24     // 16 node feats + 3 agg_s + 1 cnt_s + 3 agg_r + 1 cnt_r
#define JP (L / 2)  // 64 packed hidden-unit pairs
#define NPAIR (NN / 2)

// Scratch (__device__ globals; zero-initialized at module load).
// INVARIANT: g_agg is all-zero at entry of every kernel_launch execution —
// node_kernel re-zeroes each slot after consuming it.
__device__ float g_agg[NN * 8];       // per node: {s0,s1,s2,cnt_s, r0,r1,r2,cnt_r}
__device__ float g_W1eff[L * KEFF];   // [j*24+k] folded layer-1 weight
__device__ float g_b1eff[L];          // folded layer-1 bias
__device__ float g_w2d[L];            // W2 @ W_dn
__device__ float g_cd[1];             // b2.W_dn + b_dn

// f32x2 packed helpers ------------------------------------------------------
__device__ __forceinline__ unsigned long long pk2(float lo, float hi) {
    unsigned long long r;
    asm("mov.b64 %0, {%1, %2};" : "=l"(r) : "f"(lo), "f"(hi));
    return r;
}
__device__ __forceinline__ void upk2(unsigned long long v, float& lo, float& hi) {
    asm("mov.b64 {%0, %1}, %2;" : "=f"(lo), "=f"(hi) : "l"(v));
}
#define FMA2(d, a, b, c) \
    asm("fma.rn.f32x2 %0, %1, %2, %3;" : "=l"(d) : "l"(a), "l"(b), "l"(c))
#define ADD2(d, a, b) \
    asm("add.rn.f32x2 %0, %1, %2;" : "=l"(d) : "l"(a), "l"(b))

__device__ __forceinline__ float warp_sum(float v) {
#pragma unroll
    for (int o = 16; o; o >>= 1) v += __shfl_xor_sync(0xffffffffu, v, o);
    return v;
}

// ---------------------------------------------------------------------------
// Edge pass + embedded prep folds (R16 coalesced folds, unchanged).
__global__ __launch_bounds__(256) void edge_kernel(
    const float* __restrict__ edges, const int* __restrict__ senders,
    const int* __restrict__ receivers, float* __restrict__ edges_out,
    const float* __restrict__ g, const float* __restrict__ W_en,
    const float* __restrict__ b_en, const float* __restrict__ W_ee,
    const float* __restrict__ b_ee, const float* __restrict__ W1,
    const float* __restrict__ b1, const float* __restrict__ W2,
    const float* __restrict__ b2, const float* __restrict__ W_dn,
    const float* __restrict__ b_dn, const float* __restrict__ W_de,
    const float* __restrict__ b_de) {
    __shared__ float s_edec[4];
    int tid = threadIdx.x;
    int lane = tid & 31;
    int warp = tid >> 5;

    if (warp < 4) {
        float acc = 0.f;
        const float* A = (warp < 3) ? (W_ee + warp * L) : b_ee;
#pragma unroll
        for (int q = 0; q < 4; q++) {
            int m = lane + 32 * q;
            acc += A[m] * W_de[m];
        }
        acc = warp_sum(acc);
        if (lane == 0) s_edec[warp] = (warp == 3) ? acc + b_de[0] : acc;
    }

    int gw = blockIdx.x * 8 + warp;
    if (gw < 96) {  // W1eff[j][k], warp = (k, jg), lane = j (coalesced)
        int k = gw >> 2;
        int jg = gw & 3;
        int j = jg * 32 + lane;
        const float* A;
        int base;
        if (k < 16)      { A = W_en + k * L;        base = 0; }
        else if (k < 19) { A = W_ee + (k - 16) * L; base = L; }
        else if (k == 19){ A = b_ee;                base = L; }
        else if (k < 23) { A = W_ee + (k - 20) * L; base = 2 * L; }
        else             { A = b_ee;                base = 2 * L; }
        float acc = 0.f;
#pragma unroll 8
        for (int m = 0; m < L; m++)
            acc += A[m] * W1[(size_t)(base + m) * L + j];
        g_W1eff[j * KEFF + k] = acc;
    } else if (gw < 100) {  // b1eff[j]
        int j = (gw - 96) * 32 + lane;
        float acc = b1[j];
#pragma unroll 8
        for (int m = 0; m < L; m++) acc += b_en[m] * W1[(size_t)m * L + j];
#pragma unroll
        for (int m = 0; m < 8; m++)
            acc += g[m] * W1[(size_t)(3 * L + m) * L + j];
        g_b1eff[j] = acc;
    } else if (gw < 228) {  // w2d[k]
        int k = gw - 100;
        float acc = 0.f;
#pragma unroll
        for (int q = 0; q < 4; q++) {
            int j = lane + 32 * q;
            acc += W2[(size_t)k * L + j] * W_dn[j];
        }
        acc = warp_sum(acc);
        if (lane == 0) g_w2d[k] = acc;
    } else if (gw == 228) {  // cd
        float acc = 0.f;
#pragma unroll
        for (int q = 0; q < 4; q++) {
            int j = lane + 32 * q;
            acc += b2[j] * W_dn[j];
        }
        acc = warp_sum(acc);
        if (lane == 0) g_cd[0] = acc + b_dn[0];
    }
    __syncthreads();

    int e = blockIdx.x * blockDim.x + tid;
    if (e >= NE) return;

    float w0 = s_edec[0], w1 = s_edec[1], w2 = s_edec[2], c = s_edec[3];

    float x0 = __ldg(edges + 3 * e + 0);
    float x1 = __ldg(edges + 3 * e + 1);
    float x2 = __ldg(edges + 3 * e + 2);
    int s = senders[e];
    int r = receivers[e];

    float* ps = g_agg + (size_t)8 * s;
    float* pr = g_agg + (size_t)8 * r + 4;
    asm volatile("red.global.add.v4.f32 [%0], {%1, %2, %3, %4};" ::"l"(ps),
                 "f"(x0), "f"(x1), "f"(x2), "f"(1.0f)
                 : "memory");
    asm volatile("red.global.add.v4.f32 [%0], {%1, %2, %3, %4};" ::"l"(pr),
                 "f"(x0), "f"(x1), "f"(x2), "f"(1.0f)
                 : "memory");

    edges_out[e] = fmaf(x0, w0, fmaf(x1, w1, fmaf(x2, w2, c)));
}

// ---------------------------------------------------------------------------
// Node pass: TWO nodes per thread (halves smem-crossbar weight delivery, the
// measured 17.6us floor at 1 node/thread) + software-pipelined wA/wB weight
// double-buffer (hides LDS latency; proven structure in R16) + 4 independent
// FMA2 chains per jp. Block 64 -> grid 391 CTAs.
__global__ __launch_bounds__(64) void node_kernel(
    const float* __restrict__ nodes, float* __restrict__ nodes_out) {
    __shared__ unsigned long long sWp[JP * KEFF];  // {w[2j][k], w[2j+1][k]}, 12 KB
    __shared__ unsigned long long sBp[JP];
    __shared__ unsigned long long sDp[JP];

    int tid = threadIdx.x;
    for (int i = tid; i < JP * KEFF; i += 64) {
        int jp = i / KEFF;
        int k = i - jp * KEFF;
        sWp[i] = pk2(g_W1eff[(2 * jp) * KEFF + k], g_W1eff[(2 * jp + 1) * KEFF + k]);
    }
    if (tid < JP) {
        sBp[tid] = pk2(g_b1eff[2 * tid], g_b1eff[2 * tid + 1]);
        sDp[tid] = pk2(g_w2d[2 * tid], g_w2d[2 * tid + 1]);
    }
    __syncthreads();

    int t = blockIdx.x * 64 + tid;  // pair index
    if (t >= NPAIR) return;
    int n0 = 2 * t;

    // 24 inputs per node, splat-packed {x,x}; re-zero agg slots after reading.
    unsigned long long inA[KEFF], inB[KEFF];
    {
        const float4* np = reinterpret_cast<const float4*>(nodes + (size_t)n0 * 16);
#pragma unroll
        for (int q = 0; q < 4; q++) {
            float4 va = __ldg(np + q);
            float4 vb = __ldg(np + 4 + q);
            inA[4 * q + 0] = pk2(va.x, va.x);
            inA[4 * q + 1] = pk2(va.y, va.y);
            inA[4 * q + 2] = pk2(va.z, va.z);
            inA[4 * q + 3] = pk2(va.w, va.w);
            inB[4 * q + 0] = pk2(vb.x, vb.x);
            inB[4 * q + 1] = pk2(vb.y, vb.y);
            inB[4 * q + 2] = pk2(vb.z, vb.z);
            inB[4 * q + 3] = pk2(vb.w, vb.w);
        }
        float4* pa = reinterpret_cast<float4*>(g_agg + (size_t)8 * n0);
        float4 a0 = pa[0], a1 = pa[1], b0 = pa[2], b1 = pa[3];
        float4 z = make_float4(0.f, 0.f, 0.f, 0.f);
        pa[0] = z; pa[1] = z; pa[2] = z; pa[3] = z;
        inA[16] = pk2(a0.x, a0.x); inA[17] = pk2(a0.y, a0.y);
        inA[18] = pk2(a0.z, a0.z); inA[19] = pk2(a0.w, a0.w);
        inA[20] = pk2(a1.x, a1.x); inA[21] = pk2(a1.y, a1.y);
        inA[22] = pk2(a1.z, a1.z); inA[23] = pk2(a1.w, a1.w);
        inB[16] = pk2(b0.x, b0.x); inB[17] = pk2(b0.y, b0.y);
        inB[18] = pk2(b0.z, b0.z); inB[19] = pk2(b0.w, b0.w);
        inB[20] = pk2(b1.x, b1.x); inB[21] = pk2(b1.y, b1.y);
        inB[22] = pk2(b1.z, b1.z); inB[23] = pk2(b1.w, b1.w);
    }

    const ulonglong2* wr = reinterpret_cast<const ulonglong2*>(sWp);
    ulonglong2 wA[12], wB[12];
#pragma unroll
    for (int q = 0; q < 12; q++) wA[q] = wr[q];  // jp 0

    unsigned long long outAE = 0, outAO = 0, outBE = 0, outBO = 0;

    for (int jp = 0; jp < JP; jp += 2) {
        // prefetch jp+1 into wB
#pragma unroll
        for (int q = 0; q < 12; q++) wB[q] = wr[(jp + 1) * 12 + q];

        // compute jp with wA (both nodes, 4 chains)
        {
            unsigned long long bs = sBp[jp];
            unsigned long long aA0 = bs, aA1 = 0, aB0 = bs, aB1 = 0;
#pragma unroll
            for (int q = 0; q < 6; q++) {
                FMA2(aA0, inA[4 * q + 0], wA[2 * q].x, aA0);
                FMA2(aB0, inB[4 * q + 0], wA[2 * q].x, aB0);
                FMA2(aA1, inA[4 * q + 1], wA[2 * q].y, aA1);
                FMA2(aB1, inB[4 * q + 1], wA[2 * q].y, aB1);
                FMA2(aA0, inA[4 * q + 2], wA[2 * q + 1].x, aA0);
                FMA2(aB0, inB[4 * q + 2], wA[2 * q + 1].x, aB0);
                FMA2(aA1, inA[4 * q + 3], wA[2 * q + 1].y, aA1);
                FMA2(aB1, inB[4 * q + 3], wA[2 * q + 1].y, aB1);
            }
            unsigned long long dv = sDp[jp];
            unsigned long long accA, accB;
            ADD2(accA, aA0, aA1);
            ADD2(accB, aB0, aB1);
            float lo, hi;
            upk2(accA, lo, hi);
            unsigned long long rA = pk2(fmaxf(lo, 0.f), fmaxf(hi, 0.f));
            upk2(accB, lo, hi);
            unsigned long long rB = pk2(fmaxf(lo, 0.f), fmaxf(hi, 0.f));
            FMA2(outAE, rA, dv, outAE);
            FMA2(outBE, rB, dv, outBE);
        }

        // prefetch jp+2 into wA (wrap on last iter; harmless extra loads)
#pragma unroll
        for (int q = 0; q < 12; q++) wA[q] = wr[((jp + 2) & (JP - 1)) * 12 + q];

        // compute jp+1 with wB
        {
            unsigned long long bs = sBp[jp + 1];
            unsigned long long aA0 = bs, aA1 = 0, aB0 = bs, aB1 = 0;
#pragma unroll
            for (int q = 0; q < 6; q++) {
                FMA2(aA0, inA[4 * q + 0], wB[2 * q].x, aA0);
                FMA2(aB0, inB[4 * q + 0], wB[2 * q].x, aB0);
                FMA2(aA1, inA[4 * q + 1], wB[2 * q].y, aA1);
                FMA2(aB1, inB[4 * q + 1], wB[2 * q].y, aB1);
                FMA2(aA0, inA[4 * q + 2], wB[2 * q + 1].x, aA0);
                FMA2(aB0, inB[4 * q + 2], wB[2 * q + 1].x, aB0);
                FMA2(aA1, inA[4 * q + 3], wB[2 * q + 1].y, aA1);
                FMA2(aB1, inB[4 * q + 3], wB[2 * q + 1].y, aB1);
            }
            unsigned long long dv = sDp[jp + 1];
            unsigned long long accA, accB;
            ADD2(accA, aA0, aA1);
            ADD2(accB, aB0, aB1);
            float lo, hi;
            upk2(accA, lo, hi);
            unsigned long long rA = pk2(fmaxf(lo, 0.f), fmaxf(hi, 0.f));
            upk2(accB, lo, hi);
            unsigned long long rB = pk2(fmaxf(lo, 0.f), fmaxf(hi, 0.f));
            FMA2(outAO, rA, dv, outAO);
            FMA2(outBO, rB, dv, outBO);
        }
    }

    unsigned long long outA, outB;
    ADD2(outA, outAE, outAO);
    ADD2(outB, outBE, outBO);
    float cd = g_cd[0];
    float a0, a1, b0, b1;
    upk2(outA, a0, a1);
    upk2(outB, b0, b1);
    *reinterpret_cast<float2*>(nodes_out + n0) =
        make_float2(a0 + a1 + cd, b0 + b1 + cd);
}

// ---------------------------------------------------------------------------
extern "C" void kernel_launch(void* const* d_in, const int* in_sizes, int n_in,
                              void* d_out, int out_size) {
    const float* nodes     = (const float*)d_in[0];
    const float* edges     = (const float*)d_in[1];
    const float* globals_  = (const float*)d_in[2];
    const int*   senders   = (const int*)d_in[3];
    const int*   receivers = (const int*)d_in[4];
    const float* W_en = (const float*)d_in[5];
    const float* b_en = (const float*)d_in[6];
    const float* W_ee = (const float*)d_in[7];
    const float* b_ee = (const float*)d_in[8];
    const float* W1   = (const float*)d_in[9];
    const float* b1   = (const float*)d_in[10];
    const float* W2   = (const float*)d_in[11];
    const float* b2   = (const float*)d_in[12];
    const float* W_dn = (const float*)d_in[13];
    const float* b_dn = (const float*)d_in[14];
    const float* W_de = (const float*)d_in[15];
    const float* b_de = (const float*)d_in[16];

    float* out = (float*)d_out;
    float* nodes_out = out;          // [50000]
    float* edges_out = out + NN;     // [800000]

    // NOTE: no memset — g_agg starts zeroed (module load) and node_kernel
    // re-zeroes each slot after consuming it, so every execution (first run,
    // capture, and all graph replays) sees a zeroed buffer.
    edge_kernel<<<(NE + 255) / 256, 256>>>(
        edges, senders, receivers, edges_out, globals_, W_en, b_en, W_ee, b_ee,
        W1, b1, W2, b2, W_dn, b_dn, W_de, b_de);
    node_kernel<<<(NPAIR + 63) / 64, 64>>>(nodes, nodes_out);
}